// round 6
// baseline (speedup 1.0000x reference)
#include <cuda_runtime.h>

// InverseHaar: input (B=16, C=256, H=128, W=128) fp32, C = 4 bands x G=64 groups.
// Output (B=16, G=64, 2H=256, 2W=256) fp32.
//
// Persistent grid-stride variant of the R2/R5 shape: 608 resident CTAs
// (4/SM x 152 SMs) loop over 8192 tile-chunks. Per work item, lane l of a
// warp owns input w pairs {2l,2l+1} and {64+2l,64+2l+1} of one (b,g,h) row:
// 8 front-batched LDG.64 (512B/warp/band), 4 STG.128 each warp-contiguous
// 512B (2KB sequential output per warp). Single wave -> no wave transitions.

#define B_  16
#define G_  64
#define H_  128
#define W_  128
#define HW_ (H_ * W_)              // 16384
#define BAND_STRIDE_ (G_ * HW_)    // 1048576 floats between bands (same b)
#define OW_ (2 * W_)               // 256 output width
#define OH_ (2 * H_)               // 256 output height

#define NCHUNKS_ 8192              // total 512-thread work chunks
#define BLOCK_   512
#define GRID_    608               // 152 SMs x 4 CTAs (single wave on GB300)

__global__ void __launch_bounds__(BLOCK_) inverse_haar_kernel(
    const float2* __restrict__ in,   // viewed as float2
    float4* __restrict__ out)        // viewed as float4
{
    const long S    = BAND_STRIDE_ / 2;   // band stride in float2 units
    const int  HALF = 32;                 // second half-row offset (w=64)
    const float Q = 0.25f;

    for (int chunk = blockIdx.x; chunk < NCHUNKS_; chunk += GRID_) {
        int idx = chunk * BLOCK_ + threadIdx.x;

        int l  = idx & 31;            // lane-role within a row
        int t  = idx >> 5;
        int h  = t & (H_ - 1);
        t >>= 7;
        int g  = t & (G_ - 1);
        int b  = t >> 6;

        // Input base in float2 units: band a, (b,g,h) row, pair l (w=2l,2l+1)
        long base = ((long)(b * 4) * G_ + g) * (HW_ / 2) + (long)h * (W_ / 2) + l;

        // 8 independent streaming loads -> MLP=8
        float2 a0 = __ldcs(&in[base]);
        float2 a1 = __ldcs(&in[base + HALF]);
        float2 h0 = __ldcs(&in[base + S]);
        float2 h1 = __ldcs(&in[base + S + HALF]);
        float2 v0 = __ldcs(&in[base + 2 * S]);
        float2 v1 = __ldcs(&in[base + 2 * S + HALF]);
        float2 d0 = __ldcs(&in[base + 3 * S]);
        float2 d1 = __ldcs(&in[base + 3 * S + HALF]);

        // group 0: w = 2l (x), 2l+1 (y)
        float tl0x = (a0.x + h0.x + v0.x + d0.x) * Q;
        float tr0x = (a0.x - h0.x + v0.x - d0.x) * Q;
        float bl0x = (a0.x + h0.x - v0.x - d0.x) * Q;
        float br0x = (a0.x - h0.x - v0.x + d0.x) * Q;

        float tl0y = (a0.y + h0.y + v0.y + d0.y) * Q;
        float tr0y = (a0.y - h0.y + v0.y - d0.y) * Q;
        float bl0y = (a0.y + h0.y - v0.y - d0.y) * Q;
        float br0y = (a0.y - h0.y - v0.y + d0.y) * Q;

        // group 1: w = 64+2l (x), 64+2l+1 (y)
        float tl1x = (a1.x + h1.x + v1.x + d1.x) * Q;
        float tr1x = (a1.x - h1.x + v1.x - d1.x) * Q;
        float bl1x = (a1.x + h1.x - v1.x - d1.x) * Q;
        float br1x = (a1.x - h1.x - v1.x + d1.x) * Q;

        float tl1y = (a1.y + h1.y + v1.y + d1.y) * Q;
        float tr1y = (a1.y - h1.y + v1.y - d1.y) * Q;
        float bl1y = (a1.y + h1.y - v1.y - d1.y) * Q;
        float br1y = (a1.y - h1.y - v1.y + d1.y) * Q;

        // Output row bases (float4 units). Row has OW_/4 = 64 float4.
        long orow0 = (((long)(b * G_ + g) * OH_) + 2 * h) * (OW_ / 4) + l;
        long orow1 = orow0 + (OW_ / 4);

        // Each store: lanes 0..31 hit consecutive 16B slots -> contiguous 512B.
        __stcs(&out[orow0],      make_float4(tl0x, tr0x, tl0y, tr0y));
        __stcs(&out[orow0 + 32], make_float4(tl1x, tr1x, tl1y, tr1y));
        __stcs(&out[orow1],      make_float4(bl0x, br0x, bl0y, br0y));
        __stcs(&out[orow1 + 32], make_float4(bl1x, br1x, bl1y, br1y));
    }
}

extern "C" void kernel_launch(void* const* d_in, const int* in_sizes, int n_in,
                              void* d_out, int out_size)
{
    const float2* in = (const float2*)d_in[0];
    float4* out = (float4*)d_out;

    inverse_haar_kernel<<<GRID_, BLOCK_>>>(in, out);
}

// round 7
// speedup vs baseline: 1.1041x; 1.1041x over previous
#include <cuda_runtime.h>

// InverseHaar: input (B=16, C=256, H=128, W=128) fp32, C = 4 bands x G=64 groups.
// Output (B=16, G=64, 2H=256, 2W=256) fp32.
//
// Best measured shape (R3): one thread per (b, g, h, half, l). Lane l handles
// input w in {2l, 2l+1} of the `half`-th half-row: 4 front-batched LDG.64
// streaming loads (256B/warp/band), 2 STG.128 stores each warp-contiguous
// 512B. Stores use DEFAULT cache policy (not .cs) to let L2 batch writebacks.

#define B_  16
#define G_  64
#define H_  128
#define W_  128
#define HW_ (H_ * W_)              // 16384
#define BAND_STRIDE_ (G_ * HW_)    // 1048576 floats between bands (same b)
#define OW_ (2 * W_)               // 256 output width
#define OH_ (2 * H_)               // 256 output height

__global__ void __launch_bounds__(256) inverse_haar_kernel(
    const float2* __restrict__ in,   // viewed as float2
    float4* __restrict__ out)        // viewed as float4
{
    int idx = blockIdx.x * blockDim.x + threadIdx.x;
    // total threads = B*G*H*2*32 = 8,388,608

    int l    = idx & 31;          // lane: w pair within half-row
    int t    = idx >> 5;
    int half = t & 1;             // which half of the input row (w<64 or w>=64)
    t >>= 1;
    int h    = t & (H_ - 1);
    t >>= 7;
    int g    = t & (G_ - 1);
    int b    = t >> 6;

    // Input base in float2 units: band a, (b,g,h) row, pair index half*32 + l
    long base = ((long)(b * 4) * G_ + g) * (HW_ / 2) + (long)h * (W_ / 2)
              + half * 32 + l;
    const long S = BAND_STRIDE_ / 2;   // band stride in float2 units

    // 4 independent streaming loads (MLP_p1 = 4)
    float2 va = __ldcs(&in[base]);
    float2 vh = __ldcs(&in[base + S]);
    float2 vv = __ldcs(&in[base + 2 * S]);
    float2 vd = __ldcs(&in[base + 3 * S]);

    const float Q = 0.25f;

    float tlx = (va.x + vh.x + vv.x + vd.x) * Q;
    float trx = (va.x - vh.x + vv.x - vd.x) * Q;
    float blx = (va.x + vh.x - vv.x - vd.x) * Q;
    float brx = (va.x - vh.x - vv.x + vd.x) * Q;

    float tly = (va.y + vh.y + vv.y + vd.y) * Q;
    float try_ = (va.y - vh.y + vv.y - vd.y) * Q;
    float bly = (va.y + vh.y - vv.y - vd.y) * Q;
    float bry = (va.y - vh.y - vv.y + vd.y) * Q;

    // Output row bases (float4 units). Row has OW_/4 = 64 float4.
    // This thread's float4 slot within the row: half*32 + l.
    long orow0 = (((long)(b * G_ + g) * OH_) + 2 * h) * (OW_ / 4) + half * 32 + l;
    long orow1 = orow0 + (OW_ / 4);

    // Each store: lanes 0..31 hit consecutive 16B slots -> contiguous 512B.
    // Default cache policy: L2 may hold dirty lines briefly, enabling longer
    // same-row DRAM write bursts (less R/W turnaround).
    out[orow0] = make_float4(tlx, trx, tly, try_);
    out[orow1] = make_float4(blx, brx, bly, bry);
}

extern "C" void kernel_launch(void* const* d_in, const int* in_sizes, int n_in,
                              void* d_out, int out_size)
{
    const float2* in = (const float2*)d_in[0];
    float4* out = (float4*)d_out;

    int total_threads = B_ * G_ * H_ * 2 * 32;   // 8,388,608
    int block = 256;
    int grid = total_threads / block;            // 32768
    inverse_haar_kernel<<<grid, block>>>(in, out);
}

// round 8
// speedup vs baseline: 1.1106x; 1.0059x over previous
#include <cuda_runtime.h>

// InverseHaar: input (B=16, C=256, H=128, W=128) fp32, C = 4 bands x G=64 groups.
// Output (B=16, G=64, 2H=256, 2W=256) fp32.
//
// FINAL (best measured, R3 config): one thread per (b, g, h, half, l).
// Lane l handles input w in {2l, 2l+1} of the `half`-th half-row:
//   - 4 front-batched LDG.64 streaming loads (256B/warp/band, 4 streams)
//   - 2 STG.128 streaming stores, each warp-contiguous 512B
// Kernel is pinned at the HBM mixed read/write streaming wall
// (~6.4-6.5 TB/s, ~81% DRAM-active); verified invariant to MLP (4/8/16),
// occupancy (51-86%), block size (256/512), persistence, and cache policy.

#define B_  16
#define G_  64
#define H_  128
#define W_  128
#define HW_ (H_ * W_)              // 16384
#define BAND_STRIDE_ (G_ * HW_)    // 1048576 floats between bands (same b)
#define OW_ (2 * W_)               // 256 output width
#define OH_ (2 * H_)               // 256 output height

__global__ void __launch_bounds__(256) inverse_haar_kernel(
    const float2* __restrict__ in,   // viewed as float2
    float4* __restrict__ out)        // viewed as float4
{
    int idx = blockIdx.x * blockDim.x + threadIdx.x;
    // total threads = B*G*H*2*32 = 8,388,608

    int l    = idx & 31;          // lane: w pair within half-row
    int t    = idx >> 5;
    int half = t & 1;             // which half of the input row (w<64 or w>=64)
    t >>= 1;
    int h    = t & (H_ - 1);
    t >>= 7;
    int g    = t & (G_ - 1);
    int b    = t >> 6;

    // Input base in float2 units: band a, (b,g,h) row, pair index half*32 + l
    long base = ((long)(b * 4) * G_ + g) * (HW_ / 2) + (long)h * (W_ / 2)
              + half * 32 + l;
    const long S = BAND_STRIDE_ / 2;   // band stride in float2 units

    // 4 independent streaming loads (MLP_p1 = 4)
    float2 va = __ldcs(&in[base]);
    float2 vh = __ldcs(&in[base + S]);
    float2 vv = __ldcs(&in[base + 2 * S]);
    float2 vd = __ldcs(&in[base + 3 * S]);

    const float Q = 0.25f;

    float tlx = (va.x + vh.x + vv.x + vd.x) * Q;
    float trx = (va.x - vh.x + vv.x - vd.x) * Q;
    float blx = (va.x + vh.x - vv.x - vd.x) * Q;
    float brx = (va.x - vh.x - vv.x + vd.x) * Q;

    float tly = (va.y + vh.y + vv.y + vd.y) * Q;
    float try_ = (va.y - vh.y + vv.y - vd.y) * Q;
    float bly = (va.y + vh.y - vv.y - vd.y) * Q;
    float bry = (va.y - vh.y - vv.y + vd.y) * Q;

    // Output row bases (float4 units). Row has OW_/4 = 64 float4.
    // This thread's float4 slot within the row: half*32 + l.
    long orow0 = (((long)(b * G_ + g) * OH_) + 2 * h) * (OW_ / 4) + half * 32 + l;
    long orow1 = orow0 + (OW_ / 4);

    // Each store: lanes 0..31 hit consecutive 16B slots -> contiguous 512B.
    __stcs(&out[orow0], make_float4(tlx, trx, tly, try_));
    __stcs(&out[orow1], make_float4(blx, brx, bly, bry));
}

extern "C" void kernel_launch(void* const* d_in, const int* in_sizes, int n_in,
                              void* d_out, int out_size)
{
    const float2* in = (const float2*)d_in[0];
    float4* out = (float4*)d_out;

    int total_threads = B_ * G_ * H_ * 2 * 32;   // 8,388,608
    int block = 256;
    int grid = total_threads / block;            // 32768
    inverse_haar_kernel<<<grid, block>>>(in, out);
}

// round 9
// speedup vs baseline: 1.1274x; 1.0151x over previous
#include <cuda_runtime.h>

// InverseHaar: input (B=16, C=256, H=128, W=128) fp32, C = 4 bands x G=64 groups.
// Output (B=16, G=64, 2H=256, 2W=256) fp32.
//
// FINAL (converged): one thread per (b, g, h, half, l). Lane l handles input
// w in {2l, 2l+1} of the `half`-th half-row:
//   - 4 front-batched LDG.64 streaming loads (256B/warp/band, 4 streams)
//   - 2 STG.128 streaming stores, each warp-contiguous 512B (full-line
//     coverage -> no RFO traffic)
// Pinned at the HBM3e mixed read/write streaming wall (~6.4-6.5 TB/s, ~81%
// DRAM-active). Verified invariant to MLP (4/8/16), occupancy (51-86%),
// block size (256/512), persistent scheduling, and L2 cache policy.
// All addressing in 32-bit (max offset 2^27 elements < 2^31).

#define B_  16
#define G_  64
#define H_  128
#define W_  128
#define HW_ (H_ * W_)              // 16384
#define BAND_STRIDE_ (G_ * HW_)    // 1048576 floats between bands (same b)
#define OW_ (2 * W_)               // 256 output width
#define OH_ (2 * H_)               // 256 output height

__global__ void __launch_bounds__(256) inverse_haar_kernel(
    const float2* __restrict__ in,   // viewed as float2
    float4* __restrict__ out)        // viewed as float4
{
    unsigned idx = blockIdx.x * blockDim.x + threadIdx.x;
    // total threads = B*G*H*2*32 = 8,388,608

    unsigned l    = idx & 31;       // lane: w pair within half-row
    unsigned t    = idx >> 5;
    unsigned half = t & 1;          // which half of the input row (w<64 or w>=64)
    t >>= 1;
    unsigned h    = t & (H_ - 1);
    t >>= 7;
    unsigned g    = t & (G_ - 1);
    unsigned b    = t >> 6;

    // Input base in float2 units: band a, (b,g,h) row, pair index half*32 + l.
    // Max value: 16*4*64*8192 + ... < 2^27, fits comfortably in 32 bits.
    unsigned base = (b * 4 * G_ + g) * (HW_ / 2) + h * (W_ / 2) + half * 32 + l;
    const unsigned S = BAND_STRIDE_ / 2;   // band stride in float2 units

    // 4 independent streaming loads (MLP_p1 = 4)
    float2 va = __ldcs(&in[base]);
    float2 vh = __ldcs(&in[base + S]);
    float2 vv = __ldcs(&in[base + 2 * S]);
    float2 vd = __ldcs(&in[base + 3 * S]);

    const float Q = 0.25f;

    float tlx = (va.x + vh.x + vv.x + vd.x) * Q;
    float trx = (va.x - vh.x + vv.x - vd.x) * Q;
    float blx = (va.x + vh.x - vv.x - vd.x) * Q;
    float brx = (va.x - vh.x - vv.x + vd.x) * Q;

    float tly = (va.y + vh.y + vv.y + vd.y) * Q;
    float try_ = (va.y - vh.y + vv.y - vd.y) * Q;
    float bly = (va.y + vh.y - vv.y - vd.y) * Q;
    float bry = (va.y - vh.y - vv.y + vd.y) * Q;

    // Output row bases (float4 units). Row has OW_/4 = 64 float4.
    // This thread's float4 slot within the row: half*32 + l.
    // Max value: 64M/4 = 2^24, fits in 32 bits.
    unsigned orow0 = ((b * G_ + g) * OH_ + 2 * h) * (OW_ / 4) + half * 32 + l;
    unsigned orow1 = orow0 + (OW_ / 4);

    // Each store: lanes 0..31 hit consecutive 16B slots -> contiguous 512B.
    __stcs(&out[orow0], make_float4(tlx, trx, tly, try_));
    __stcs(&out[orow1], make_float4(blx, brx, bly, bry));
}

extern "C" void kernel_launch(void* const* d_in, const int* in_sizes, int n_in,
                              void* d_out, int out_size)
{
    const float2* in = (const float2*)d_in[0];
    float4* out = (float4*)d_out;

    int total_threads = B_ * G_ * H_ * 2 * 32;   // 8,388,608
    int block = 256;
    int grid = total_threads / block;            // 32768
    inverse_haar_kernel<<<grid, block>>>(in, out);
}